// round 9
// baseline (speedup 1.0000x reference)
#include <cuda_runtime.h>

// AlphaCompositor: N=8, K=8, H=512, W=512, C=4, P=100000
// out = [images (N,C,H,W) f32] ++ [!bg_mask (N,H,W) as f32]
//
// At the L1TEX address-divergence floor (16.8M random 16B gathers, ~1
// line-visit/cyc/SM). This revision removes the remaining non-floor costs:
// single-wave persistent grid (no wave transitions / tail) + vectorized pack.

#define NN 8
#define KK 8
#define HH 512
#define WW 512
#define CC 4
#define PP 100000
#define HW (HH * WW)

#define NSM 148                       // B200 SMs
#define CTAS_PER_SM 6
#define NBLOCKS (NSM * CTAS_PER_SM)   // 888: single wave at 6 CTAs/SM
#define NTHREADS 256

// AoS-packed point features, one float4 per point (1.6 MB, L2-resident).
__device__ float4 g_packed[PP];

// Vectorized pack: each thread transposes 4 points (float4 per channel in,
// 4x float4 out, all 16B-coalesced). P = 100000 is divisible by 4.
__global__ void pack_kernel(const float* __restrict__ ptclds) {
    int p4 = blockIdx.x * blockDim.x + threadIdx.x;   // point group [0, P/4)
    if (p4 < PP / 4) {
        const int p = p4 * 4;
        float4 c0 = *reinterpret_cast<const float4*>(ptclds + 0 * PP + p);
        float4 c1 = *reinterpret_cast<const float4*>(ptclds + 1 * PP + p);
        float4 c2 = *reinterpret_cast<const float4*>(ptclds + 2 * PP + p);
        float4 c3 = *reinterpret_cast<const float4*>(ptclds + 3 * PP + p);
        g_packed[p + 0] = make_float4(c0.x, c1.x, c2.x, c3.x);
        g_packed[p + 1] = make_float4(c0.y, c1.y, c2.y, c3.y);
        g_packed[p + 2] = make_float4(c0.z, c1.z, c2.z, c3.z);
        g_packed[p + 3] = make_float4(c0.w, c1.w, c2.w, c3.w);
    }
}

// Persistent single-wave grid; one pixel per thread per iteration.
__global__ __launch_bounds__(NTHREADS, CTAS_PER_SM) void composite_kernel(
    const int*   __restrict__ pix,
    const float* __restrict__ alphas,
    float*       __restrict__ out,
    int write_mask)
{
    const int total  = NN * HW;
    const int stride = NBLOCKS * NTHREADS;

    for (int t = blockIdx.x * NTHREADS + threadIdx.x; t < total; t += stride) {
        const int n  = t >> 18;          // / HW  (HW = 262144 = 2^18)
        const int hw = t & (HW - 1);
        const long nbase = (long)n * KK * HW + hw;

        // ---- Phase 1: streaming loads, evict-first (protect gather table) ----
        int   idx[KK];
        float al[KK];
#pragma unroll
        for (int k = 0; k < KK; k++) {
            idx[k] = __ldcs(pix    + nbase + (long)k * HW);
            al[k]  = __ldcs(alphas + nbase + (long)k * HW);
        }

        // ---- Phase 2: blend weights (pure FMA chain) ----
        // Invalid entries (idx<0) get weight exactly 0, so the clamped gather
        // below contributes exactly 0 -> branch-free and exact.
        float w[KK];
        {
            float trans = 1.0f;
#pragma unroll
            for (int k = 0; k < KK; k++) {
                float a = (idx[k] >= 0) ? al[k] : 0.0f;
                w[k] = a * trans;
                trans *= (1.0f - a);
            }
        }

        // ---- Phase 3: branch-free gather + accumulate ----
        float ax = 0.f, ay = 0.f, az = 0.f, aw = 0.f;
#pragma unroll
        for (int k = 0; k < KK; k++) {
            const int i = max(idx[k], 0);      // clamp: invalid -> point 0 (w=0)
            float4 f = __ldg(&g_packed[i]);
            ax = fmaf(w[k], f.x, ax);
            ay = fmaf(w[k], f.y, ay);
            az = fmaf(w[k], f.z, az);
            aw = fmaf(w[k], f.w, aw);
        }

        // Background pixel: first index negative -> images = BG = (0,0,0,1)
        const bool bg = (idx[0] < 0);
        if (bg) { ax = 0.f; ay = 0.f; az = 0.f; aw = 1.f; }

        // ---- Stores: evict-first (pure streaming output) ----
        const long obase = (long)n * CC * HW + hw;
        __stcs(out + obase + 0L * HW, ax);
        __stcs(out + obase + 1L * HW, ay);
        __stcs(out + obase + 2L * HW, az);
        __stcs(out + obase + 3L * HW, aw);

        if (write_mask)
            __stcs(out + (long)NN * CC * HW + t, bg ? 0.f : 1.f);
    }
}

extern "C" void kernel_launch(void* const* d_in, const int* in_sizes, int n_in,
                              void* d_out, int out_size) {
    const int*   pix    = (const int*)d_in[0];    // pix_idxs int32 [N,K,H,W]
    const float* alphas = (const float*)d_in[1];  // alphas  f32   [N,K,H,W]
    const float* ptclds = (const float*)d_in[2];  // ptclds  f32   [C,P]
    float* out = (float*)d_out;

    const int images_elems = NN * CC * HW;
    const int write_mask   = (out_size > images_elems) ? 1 : 0;

    pack_kernel<<<(PP / 4 + 255) / 256, 256>>>(ptclds);
    composite_kernel<<<NBLOCKS, NTHREADS>>>(pix, alphas, out, write_mask);
}